// round 1
// baseline (speedup 1.0000x reference)
#include <cuda_runtime.h>
#include <cstdint>

// SGNS loss:
//   out[n] = -( logsig(<emb[tgt[n]], out_w[ctx[n]]>) + sum_k logsig(-<emb[tgt[n]], out_w[neg[n,k]]>) )
// V=100000, D=128, N=262144, K=5. One warp per pair; float4 per lane (32*16B = 512B row).

#define D 128
#define KNEG 5

__device__ __forceinline__ float log_sigmoid(float x) {
    // stable: min(x,0) - log1p(exp(-|x|))
    return fminf(x, 0.0f) - log1pf(__expf(-fabsf(x)));
}

__global__ void __launch_bounds__(256) sgns_loss_kernel(
    const float* __restrict__ emb,
    const float* __restrict__ out_w,
    const int*   __restrict__ tgt_ids,
    const int*   __restrict__ ctx_ids,
    const int*   __restrict__ neg_ids,
    float*       __restrict__ out,
    int N)
{
    const int warp = (blockIdx.x * blockDim.x + threadIdx.x) >> 5;
    const int lane = threadIdx.x & 31;
    if (warp >= N) return;

    // Fetch all 7 indices up front (independent loads, broadcast through L1).
    const int t = __ldg(tgt_ids + warp);
    const int c = __ldg(ctx_ids + warp);
    int nidx[KNEG];
#pragma unroll
    for (int k = 0; k < KNEG; k++)
        nidx[k] = __ldg(neg_ids + (size_t)warp * KNEG + k);

    // input embedding row: lane l holds floats [4l, 4l+4)
    const float4 iv = __ldg(reinterpret_cast<const float4*>(emb + (size_t)t * D) + lane);

    float s[1 + KNEG];
    {
        const float4 pv = __ldg(reinterpret_cast<const float4*>(out_w + (size_t)c * D) + lane);
        s[0] = iv.x * pv.x + iv.y * pv.y + iv.z * pv.z + iv.w * pv.w;
    }
#pragma unroll
    for (int k = 0; k < KNEG; k++) {
        const float4 nv = __ldg(reinterpret_cast<const float4*>(out_w + (size_t)nidx[k] * D) + lane);
        s[1 + k] = iv.x * nv.x + iv.y * nv.y + iv.z * nv.z + iv.w * nv.w;
    }

    // 6 butterfly reductions
#pragma unroll
    for (int j = 0; j < 1 + KNEG; j++) {
#pragma unroll
        for (int off = 16; off > 0; off >>= 1)
            s[j] += __shfl_xor_sync(0xFFFFFFFFu, s[j], off);
    }

    if (lane == 0) {
        float loss = -log_sigmoid(s[0]);
#pragma unroll
        for (int k = 0; k < KNEG; k++)
            loss -= log_sigmoid(-s[1 + k]);
        out[warp] = loss;
    }
}

extern "C" void kernel_launch(void* const* d_in, const int* in_sizes, int n_in,
                              void* d_out, int out_size) {
    const float* emb     = (const float*)d_in[0];
    const float* out_w   = (const float*)d_in[1];
    const int*   tgt_ids = (const int*)d_in[2];
    const int*   ctx_ids = (const int*)d_in[3];
    const int*   neg_ids = (const int*)d_in[4];
    float*       out     = (float*)d_out;

    const int N = in_sizes[2];              // number of pairs
    const int threads = 256;                // 8 warps = 8 pairs per block
    const int pairs_per_block = threads / 32;
    const int blocks = (N + pairs_per_block - 1) / pairs_per_block;
    sgns_loss_kernel<<<blocks, threads>>>(emb, out_w, tgt_ids, ctx_ids, neg_ids, out, N);
}

// round 2
// speedup vs baseline: 1.4336x; 1.4336x over previous
#include <cuda_runtime.h>
#include <cstdint>

// SGNS loss, 8 lanes per pair (4 pairs per warp).
// Each lane holds 16 floats (4 x float4) of the D=128 row; one LDG.128
// instruction per row covers one 128B line per pair-group (perfect sectors).
// Reduction: 3 butterfly stages within 8-lane groups, shared across 4 pairs.

#define D 128
#define KNEG 5
#define LPP 8          // lanes per pair
#define VPL 4          // float4 vectors per lane (D/4/LPP)

__device__ __forceinline__ float log_sigmoid(float x) {
    // stable: min(x,0) - log1p(exp(-|x|))
    return fminf(x, 0.0f) - log1pf(__expf(-fabsf(x)));
}

__device__ __forceinline__ float dot16(const float4* a, const float4* b) {
    float s = 0.f;
#pragma unroll
    for (int i = 0; i < VPL; i++) {
        s = fmaf(a[i].x, b[i].x, s);
        s = fmaf(a[i].y, b[i].y, s);
        s = fmaf(a[i].z, b[i].z, s);
        s = fmaf(a[i].w, b[i].w, s);
    }
    return s;
}

__global__ void __launch_bounds__(256) sgns_loss_kernel(
    const float* __restrict__ emb,
    const float* __restrict__ out_w,
    const int*   __restrict__ tgt_ids,
    const int*   __restrict__ ctx_ids,
    const int*   __restrict__ neg_ids,
    float*       __restrict__ out,
    int N)
{
    const int tid  = blockIdx.x * blockDim.x + threadIdx.x;
    const int pair = tid >> 3;               // 8 lanes per pair
    const int lane = threadIdx.x & (LPP - 1);
    if (pair >= N) return;

    // indices (all 8 lanes load same address -> single coalesced request)
    const int t = __ldg(tgt_ids + pair);
    const int c = __ldg(ctx_ids + pair);
    int nidx[KNEG];
#pragma unroll
    for (int k = 0; k < KNEG; k++)
        nidx[k] = __ldg(neg_ids + (size_t)pair * KNEG + k);

    // input row: lane holds float4 slots {lane, lane+8, lane+16, lane+24}
    const float4* irow = reinterpret_cast<const float4*>(emb + (size_t)t * D);
    float4 iv[VPL];
#pragma unroll
    for (int i = 0; i < VPL; i++)
        iv[i] = __ldg(irow + lane + LPP * i);

    // software-pipelined walk over the 6 out_w rows (ctx + 5 neg)
    const float4* rows[1 + KNEG];
    rows[0] = reinterpret_cast<const float4*>(out_w + (size_t)c * D);
#pragma unroll
    for (int k = 0; k < KNEG; k++)
        rows[1 + k] = reinterpret_cast<const float4*>(out_w + (size_t)nidx[k] * D);

    float4 cur[VPL], nxt[VPL];
#pragma unroll
    for (int i = 0; i < VPL; i++)
        cur[i] = __ldg(rows[0] + lane + LPP * i);

    float s[1 + KNEG];
#pragma unroll
    for (int j = 0; j < 1 + KNEG; j++) {
        if (j < KNEG) {
#pragma unroll
            for (int i = 0; i < VPL; i++)
                nxt[i] = __ldg(rows[j + 1] + lane + LPP * i);
        }
        s[j] = dot16(iv, cur);
        if (j < KNEG) {
#pragma unroll
            for (int i = 0; i < VPL; i++)
                cur[i] = nxt[i];
        }
    }

    // 3-stage butterfly within 8-lane groups; one instruction serves 4 pairs
#pragma unroll
    for (int j = 0; j < 1 + KNEG; j++) {
#pragma unroll
        for (int off = LPP / 2; off > 0; off >>= 1)
            s[j] += __shfl_xor_sync(0xFFFFFFFFu, s[j], off);
    }

    if (lane == 0) {
        float loss = -log_sigmoid(s[0]);
#pragma unroll
        for (int k = 0; k < KNEG; k++)
            loss -= log_sigmoid(-s[1 + k]);
        out[pair] = loss;
    }
}

extern "C" void kernel_launch(void* const* d_in, const int* in_sizes, int n_in,
                              void* d_out, int out_size) {
    const float* emb     = (const float*)d_in[0];
    const float* out_w   = (const float*)d_in[1];
    const int*   tgt_ids = (const int*)d_in[2];
    const int*   ctx_ids = (const int*)d_in[3];
    const int*   neg_ids = (const int*)d_in[4];
    float*       out     = (float*)d_out;

    const int N = in_sizes[2];
    const int threads = 256;                  // 32 pairs per block
    const int pairs_per_block = threads / LPP;
    const int blocks = (N + pairs_per_block - 1) / pairs_per_block;
    sgns_loss_kernel<<<blocks, threads>>>(emb, out_w, tgt_ids, ctx_ids, neg_ids, out, N);
}